// round 12
// baseline (speedup 1.0000x reference)
#include <cuda_runtime.h>
#include <cstdint>

#define NSIZE   4096
#define BVAL    8
#define CVAL    32
#define MT      128              // m columns per CTA
#define NCH     128              // n per chunk
#define NCHUNKS (NSIZE / NCH)    // 32

// smem layout (bytes), double-buffered stages
#define ADJ_PITCH 544            // 136 floats: transposed read 8q+r conflict-free
#define FEA_PITCH 528            // 132 floats: frag read 4r+q conflict-free
#define ADJ_OFF   0              // 128 x 544           = 69632
#define FEAH_OFF  69632          // 32 x 528            = 16896
#define FEAL_OFF  86528          // 32 x 528            = 16896
#define EN_OFF    103424         // 128 floats          = 512
#define STAGE     104448
#define SM_TOTAL  (2 * STAGE)    // 208896 < 227KB

__device__ float    g_E[BVAL * NSIZE];
__device__ uint32_t g_feah[BVAL * CVAL * NSIZE];   // tf32 bits, hi part
__device__ uint32_t g_feal[BVAL * CVAL * NSIZE];   // tf32 bits, residual

// ---- helpers --------------------------------------------------------------
__device__ __forceinline__ uint32_t smem_u32(const void* p) {
    uint32_t a;
    asm("{ .reg .u64 t; cvta.to.shared.u64 t, %1; cvt.u32.u64 %0, t; }"
        : "=r"(a) : "l"(p));
    return a;
}
__device__ __forceinline__ uint32_t f2tf32(float f) {
    uint32_t r; asm("cvt.rna.tf32.f32 %0, %1;" : "=r"(r) : "f"(f)); return r;
}
__device__ __forceinline__ float rcpf(float f) {
    float r; asm("rcp.approx.f32 %0, %1;" : "=f"(r) : "f"(f)); return r;
}
#define CP_ASYNC16(dst, src) \
    asm volatile("cp.async.cg.shared.global [%0], [%1], 16;" \
                 :: "r"(dst), "l"(src) : "memory")
#define CP_COMMIT()  asm volatile("cp.async.commit_group;" ::: "memory")
#define CP_WAIT(n)   asm volatile("cp.async.wait_group %0;" :: "n"(n) : "memory")

__device__ __forceinline__ void mma_tf32(float c[4], uint32_t a0, uint32_t a1,
                                         uint32_t a2, uint32_t a3,
                                         uint32_t b0, uint32_t b1) {
    asm volatile(
        "mma.sync.aligned.m16n8k8.row.col.f32.tf32.tf32.f32 "
        "{%0,%1,%2,%3}, {%4,%5,%6,%7}, {%8,%9}, {%0,%1,%2,%3};"
        : "+f"(c[0]), "+f"(c[1]), "+f"(c[2]), "+f"(c[3])
        : "r"(a0), "r"(a1), "r"(a2), "r"(a3), "r"(b0), "r"(b1));
}

// ---------------------------------------------------------------------------
// Kernel 1: E[b,n] = exp(mean_c x);  fea -> tf32 hi/lo planes (exact split).
// ---------------------------------------------------------------------------
__global__ void prep_kernel(const float* __restrict__ x) {
    int t = blockIdx.x * blockDim.x + threadIdx.x;
    if (t >= BVAL * NSIZE / 4) return;
    int b = t >> 10, n4 = (t & 1023) << 2;
    const float4* xp = (const float4*)(x + (size_t)b * CVAL * NSIZE + n4);
    float4 s = make_float4(0.f, 0.f, 0.f, 0.f);
#pragma unroll
    for (int c = 0; c < CVAL; c++) {
        float4 v = xp[(size_t)c * (NSIZE / 4)];
        s.x += v.x; s.y += v.y; s.z += v.z; s.w += v.w;
        uint32_t h0 = f2tf32(v.x), h1 = f2tf32(v.y),
                 h2 = f2tf32(v.z), h3 = f2tf32(v.w);
        uint32_t l0 = f2tf32(v.x - __uint_as_float(h0));
        uint32_t l1 = f2tf32(v.y - __uint_as_float(h1));
        uint32_t l2 = f2tf32(v.z - __uint_as_float(h2));
        uint32_t l3 = f2tf32(v.w - __uint_as_float(h3));
        size_t o = (((size_t)b * CVAL + c) << 12) + n4;
        *(uint4*)(g_feah + o) = make_uint4(h0, h1, h2, h3);
        *(uint4*)(g_feal + o) = make_uint4(l0, l1, l2, l3);
    }
    const float inv = 1.0f / CVAL;
    *(float4*)(g_E + (b << 12) + n4) =
        make_float4(__expf(s.x * inv), __expf(s.y * inv),
                    __expf(s.z * inv), __expf(s.w * inv));
}

// ---------------------------------------------------------------------------
// Kernel 2: HMMA main.  D[m,c] = sum_n w(n,m) * fea[c,n];
//   w = adj[n,m] * min(Em,En)/(Em+En)   (exact closed form of ref weight)
//   out = relu(2 * D * para).  W generated straight into A fragments.
// ---------------------------------------------------------------------------
__global__ void __launch_bounds__(256, 1) gcn_hmma_kernel(
    const float* __restrict__ para,
    const float* __restrict__ adj,
    float* __restrict__ out)
{
    extern __shared__ __align__(1024) char smem[];
    const int tid = threadIdx.x, wid = tid >> 5, lid = tid & 31;
    const int q = lid & 3, r = lid >> 2;
    const int b = blockIdx.y, m0 = blockIdx.x * MT;
    const int mw = wid * 16;

    const float em0 = g_E[(b << 12) + m0 + mw + r];      // A rows m = r, r+8
    const float em1 = g_E[(b << 12) + m0 + mw + r + 8];

    float acc[4][4];
#pragma unroll
    for (int g = 0; g < 4; g++)
#pragma unroll
        for (int i = 0; i < 4; i++) acc[g][i] = 0.0f;

    // ---- prefetch chunk t into stage s -----------------------------------
    auto prefetch = [&](int t, int s) {
        char* st = smem + s * STAGE;
        const uint32_t sd = smem_u32(st);
        const int n0 = t * NCH;
        {   // adj [128 n][128 m], coalesced 16B
            int row = tid >> 1, half = tid & 1;
            const float* src = adj + (size_t)(n0 + row) * NSIZE + m0 + half * 64;
            uint32_t dst = sd + ADJ_OFF + row * ADJ_PITCH + half * 256;
#pragma unroll
            for (int j = 0; j < 16; j++) CP_ASYNC16(dst + j * 16, src + j * 4);
        }
        {   // fea hi/lo [32 c][128 n]
            int c = tid >> 3, g8 = tid & 7;
            size_t o = (((size_t)b * CVAL + c) << 12) + n0 + g8 * 16;
            uint32_t dh = sd + FEAH_OFF + c * FEA_PITCH + g8 * 64;
            uint32_t dl = sd + FEAL_OFF + c * FEA_PITCH + g8 * 64;
#pragma unroll
            for (int j = 0; j < 4; j++) {
                CP_ASYNC16(dh + j * 16, g_feah + o + j * 4);
                CP_ASYNC16(dl + j * 16, g_feal + o + j * 4);
            }
        }
        if (tid < NCH)   // En slice (plain store; ordered by __syncthreads)
            *(float*)(st + EN_OFF + tid * 4) = g_E[(b << 12) + n0 + tid];
    };

    prefetch(0, 0);
    CP_COMMIT();

    for (int t = 0; t < NCHUNKS; t++) {
        const int s = t & 1;
        if (t + 1 < NCHUNKS) { prefetch(t + 1, s ^ 1); CP_COMMIT(); CP_WAIT(1); }
        else                 { CP_WAIT(0); }
        __syncthreads();

        const char* st = smem + s * STAGE;
        const float*    adjs = (const float*)(st + ADJ_OFF);
        const uint32_t* fh   = (const uint32_t*)(st + FEAH_OFF);
        const uint32_t* fl   = (const uint32_t*)(st + FEAL_OFF);
        const float*    ens  = (const float*)(st + EN_OFF);

#pragma unroll 4
        for (int ks = 0; ks < 16; ks++) {
            const int n8 = ks * 8;
            const float en0 = ens[n8 + q];
            const float en1 = ens[n8 + q + 4];
            // adj at (n, m): transposed LDS, conflict-free (pad 136)
            const float a00 = adjs[(n8 + q)     * 136 + mw + r];
            const float a01 = adjs[(n8 + q)     * 136 + mw + r + 8];
            const float a10 = adjs[(n8 + q + 4) * 136 + mw + r];
            const float a11 = adjs[(n8 + q + 4) * 136 + mw + r + 8];
            // weights -> A fragment (a0:(r,q) a1:(r+8,q) a2:(r,q+4) a3:(r+8,q+4))
            const uint32_t A0 = f2tf32(a00 * fminf(em0, en0) * rcpf(em0 + en0));
            const uint32_t A1 = f2tf32(a01 * fminf(em1, en0) * rcpf(em1 + en0));
            const uint32_t A2 = f2tf32(a10 * fminf(em0, en1) * rcpf(em0 + en1));
            const uint32_t A3 = f2tf32(a11 * fminf(em1, en1) * rcpf(em1 + en1));

#pragma unroll
            for (int g = 0; g < 4; g++) {          // c-groups of 8
                const int cb = (g * 8 + r) * 132 + n8 + q;
                mma_tf32(acc[g], A0, A1, A2, A3, fh[cb], fh[cb + 4]);
                mma_tf32(acc[g], A0, A1, A2, A3, fl[cb], fl[cb + 4]);
            }
        }
        __syncthreads();   // stage s fully consumed before t+2 overwrites it
    }

    // ---- epilogue: relu(2 * D * para) ------------------------------------
    const int mg = m0 + mw + r;
#pragma unroll
    for (int g = 0; g < 4; g++) {
        const int c0 = g * 8 + 2 * q, c1 = c0 + 1;
        const size_t o00 = (((size_t)b * CVAL + c0) << 12) + mg;
        const size_t o10 = (((size_t)b * CVAL + c1) << 12) + mg;
        out[o00]     = fmaxf(2.0f * acc[g][0] * para[((size_t)c0 << 12) + mg],     0.0f);
        out[o10]     = fmaxf(2.0f * acc[g][1] * para[((size_t)c1 << 12) + mg],     0.0f);
        out[o00 + 8] = fmaxf(2.0f * acc[g][2] * para[((size_t)c0 << 12) + mg + 8], 0.0f);
        out[o10 + 8] = fmaxf(2.0f * acc[g][3] * para[((size_t)c1 << 12) + mg + 8], 0.0f);
    }
}

// ---------------------------------------------------------------------------
extern "C" void kernel_launch(void* const* d_in, const int* in_sizes, int n_in,
                              void* d_out, int out_size) {
    const float* x    = (const float*)d_in[0];   // [8,32,64,64]
    const float* para = (const float*)d_in[1];   // [1,32,64,64]
    const float* adj  = (const float*)d_in[2];   // [4096,4096]
    float*       out  = (float*)d_out;           // [8,32,64,64]
    (void)in_sizes; (void)n_in; (void)out_size;

    cudaFuncSetAttribute(gcn_hmma_kernel,
                         cudaFuncAttributeMaxDynamicSharedMemorySize, SM_TOTAL);

    prep_kernel<<<(BVAL * NSIZE / 4 + 255) / 256, 256>>>(x);

    dim3 grid(NSIZE / MT, BVAL);                 // 32 x 8 = 256 CTAs
    gcn_hmma_kernel<<<grid, 256, SM_TOTAL>>>(para, adj, out);
}

// round 15
// speedup vs baseline: 1.3215x; 1.3215x over previous
#include <cuda_runtime.h>
#include <cstdint>

#define NSIZE   4096
#define BVAL    8
#define CVAL    32
#define MT      128              // m columns per CTA
#define NCH     128              // n per chunk
#define NCHUNKS (NSIZE / NCH)    // 32
#define NTHR    512              // 16 warps: ks-split halves

// smem layout (bytes), double-buffered stages
#define ADJ_PITCH 544            // 136 floats: both fill + transposed read OK
#define FEA_PITCH 544            // 136 floats: float2 frag read conflict-free
#define ADJ_OFF   0              // 128 x 544 = 69632
#define FEA_OFF   69632          // 32 x 544  = 17408
#define EN_OFF    87040          // 128 floats = 512
#define STAGE     87552
#define SM_TOTAL  (2 * STAGE)    // 175104 < 227KB

__device__ float    g_E[BVAL * NSIZE];
__device__ uint32_t g_fea[BVAL * CVAL * NSIZE];  // tf32, chunk-permuted layout

// ---- helpers --------------------------------------------------------------
__device__ __forceinline__ uint32_t smem_u32(const void* p) {
    uint32_t a;
    asm("{ .reg .u64 t; cvta.to.shared.u64 t, %1; cvt.u32.u64 %0, t; }"
        : "=r"(a) : "l"(p));
    return a;
}
__device__ __forceinline__ uint32_t f2tf32(float f) {
    uint32_t r; asm("cvt.rna.tf32.f32 %0, %1;" : "=r"(r) : "f"(f)); return r;
}
__device__ __forceinline__ float rcpf(float f) {
    float r; asm("rcp.approx.f32 %0, %1;" : "=f"(r) : "f"(f)); return r;
}
#define CP_ASYNC16(dst, src) \
    asm volatile("cp.async.cg.shared.global [%0], [%1], 16;" \
                 :: "r"(dst), "l"(src) : "memory")
#define CP_COMMIT()  asm volatile("cp.async.commit_group;" ::: "memory")
#define CP_WAIT(n)   asm volatile("cp.async.wait_group %0;" :: "n"(n) : "memory")

__device__ __forceinline__ void mma_tf32(float c[4], uint32_t a0, uint32_t a1,
                                         uint32_t a2, uint32_t a3,
                                         uint32_t b0, uint32_t b1) {
    asm volatile(
        "mma.sync.aligned.m16n8k8.row.col.f32.tf32.tf32.f32 "
        "{%0,%1,%2,%3}, {%4,%5,%6,%7}, {%8,%9}, {%0,%1,%2,%3};"
        : "+f"(c[0]), "+f"(c[1]), "+f"(c[2]), "+f"(c[3])
        : "r"(a0), "r"(a1), "r"(a2), "r"(a3), "r"(b0), "r"(b1));
}

// ---------------------------------------------------------------------------
// Kernel 1: E[b,n] = exp(mean_c x); fea -> tf32, chunk-permuted so B-fragment
// pairs (k=q, k=q+4) are adjacent:  loc = ks*8 + half*4 + q  ->  ks*8 + 2q + half
// ---------------------------------------------------------------------------
__global__ void prep_kernel(const float* __restrict__ x) {
    int t = blockIdx.x * blockDim.x + threadIdx.x;
    if (t >= BVAL * NSIZE / 4) return;
    int b = t >> 10, n4 = (t & 1023) << 2;
    int loc = n4 & 127;
    // permuted base within the chunk: same ks & half for all 4 q values
    int pbase = (n4 & ~127) + (loc >> 3) * 8 + ((loc >> 2) & 1);
    const float4* xp = (const float4*)(x + (size_t)b * CVAL * NSIZE + n4);
    float4 s = make_float4(0.f, 0.f, 0.f, 0.f);
#pragma unroll
    for (int c = 0; c < CVAL; c++) {
        float4 v = xp[(size_t)c * (NSIZE / 4)];
        s.x += v.x; s.y += v.y; s.z += v.z; s.w += v.w;
        uint32_t* fp = g_fea + (((size_t)b * CVAL + c) << 12) + pbase;
        fp[0] = f2tf32(v.x); fp[2] = f2tf32(v.y);
        fp[4] = f2tf32(v.z); fp[6] = f2tf32(v.w);
    }
    const float inv = 1.0f / CVAL;
    *(float4*)(g_E + (b << 12) + n4) =
        make_float4(__expf(s.x * inv), __expf(s.y * inv),
                    __expf(s.z * inv), __expf(s.w * inv));
}

// ---------------------------------------------------------------------------
// Kernel 2: HMMA main, 16 warps, ks-split halves + smem reduction.
//   D[m,c] = sum_n adj[n,m]*min(Em,En)/(Em+En) * fea[c,n]
//   out = relu(2 * D * para)
// ---------------------------------------------------------------------------
__global__ void __launch_bounds__(NTHR, 1) gcn_hmma_kernel(
    const float* __restrict__ para,
    const float* __restrict__ adj,
    float* __restrict__ out)
{
    extern __shared__ __align__(1024) char smem[];
    const int tid = threadIdx.x, wid = tid >> 5, lid = tid & 31;
    const int q = lid & 3, r = lid >> 2;
    const int b = blockIdx.y, m0 = blockIdx.x * MT;
    const int mw = (wid & 7) * 16;        // m sub-tile (shared by wid, wid+8)
    const int h  = wid >> 3;              // ks half: 0 -> ks 0-7, 1 -> ks 8-15

    const float em0 = g_E[(b << 12) + m0 + mw + r];
    const float em1 = g_E[(b << 12) + m0 + mw + r + 8];

    float acc[4][4];
#pragma unroll
    for (int g = 0; g < 4; g++)
#pragma unroll
        for (int i = 0; i < 4; i++) acc[g][i] = 0.0f;

    auto prefetch = [&](int t, int s) {
        char* st = smem + s * STAGE;
        const uint32_t sd = smem_u32(st);
        const int n0 = t * NCH;
        {   // adj [128 n][128 m]: 512 thr x 8 chunks of 16B
            int row = tid >> 2, quarter = tid & 3;
            const float* src = adj + (size_t)(n0 + row) * NSIZE + m0 + quarter * 32;
            uint32_t dst = sd + ADJ_OFF + row * ADJ_PITCH + quarter * 128;
#pragma unroll
            for (int j = 0; j < 8; j++) CP_ASYNC16(dst + j * 16, src + j * 4);
        }
        {   // fea [32 c][128 n] (already permuted): 512 thr x 2 chunks
            int c = tid >> 4, seg = tid & 15;
            const uint32_t* src = g_fea + (((size_t)b * CVAL + c) << 12) + n0 + seg * 8;
            uint32_t dst = sd + FEA_OFF + c * FEA_PITCH + seg * 32;
            CP_ASYNC16(dst,      src);
            CP_ASYNC16(dst + 16, src + 4);
        }
        if (tid < NCH)
            *(float*)(st + EN_OFF + tid * 4) = g_E[(b << 12) + n0 + tid];
    };

    prefetch(0, 0);
    CP_COMMIT();

    for (int t = 0; t < NCHUNKS; t++) {
        const int s = t & 1;
        if (t + 1 < NCHUNKS) { prefetch(t + 1, s ^ 1); CP_COMMIT(); CP_WAIT(1); }
        else                 { CP_WAIT(0); }
        __syncthreads();

        const char* st = smem + s * STAGE;
        const float*    adjs = (const float*)(st + ADJ_OFF);
        const uint32_t* feas = (const uint32_t*)(st + FEA_OFF);
        const float*    ens  = (const float*)(st + EN_OFF);

#pragma unroll
        for (int kk = 0; kk < 8; kk++) {
            const int n8 = (h * 8 + kk) * 8;
            const float en0 = ens[n8 + q];
            const float en1 = ens[n8 + q + 4];
            const float a00 = adjs[(n8 + q)     * 136 + mw + r];
            const float a01 = adjs[(n8 + q)     * 136 + mw + r + 8];
            const float a10 = adjs[(n8 + q + 4) * 136 + mw + r];
            const float a11 = adjs[(n8 + q + 4) * 136 + mw + r + 8];
            const uint32_t A0 = f2tf32(a00 * fminf(em0, en0) * rcpf(em0 + en0));
            const uint32_t A1 = f2tf32(a01 * fminf(em1, en0) * rcpf(em1 + en0));
            const uint32_t A2 = f2tf32(a10 * fminf(em0, en1) * rcpf(em0 + en1));
            const uint32_t A3 = f2tf32(a11 * fminf(em1, en1) * rcpf(em1 + en1));

#pragma unroll
            for (int g = 0; g < 4; g++) {
                // one LDS.64: B pair (k=q, k=q+4) adjacent in permuted layout
                const uint2 bb = *(const uint2*)
                    (feas + (g * 8 + r) * 136 + n8 + q * 2);
                mma_tf32(acc[g], A0, A1, A2, A3, bb.x, bb.y);
            }
        }
        __syncthreads();
    }

    // ---- reduce ks halves: warps 8-15 -> smem, warps 0-7 add -------------
    float* red = (float*)smem;            // stage 0 area is dead now
    if (wid >= 8) {
        float* rp = red + (wid - 8) * 512;
#pragma unroll
        for (int g = 0; g < 4; g++) {
            const int c0 = g * 8 + 2 * q;
            rp[ r      * 32 + c0    ] = acc[g][0];
            rp[ r      * 32 + c0 + 1] = acc[g][1];
            rp[(r + 8) * 32 + c0    ] = acc[g][2];
            rp[(r + 8) * 32 + c0 + 1] = acc[g][3];
        }
    }
    __syncthreads();

    if (wid < 8) {
        const float* rp = red + wid * 512;
        const int mg = m0 + mw + r;
#pragma unroll
        for (int g = 0; g < 4; g++) {
            const int c0 = g * 8 + 2 * q, c1 = c0 + 1;
            const float v0 = acc[g][0] + rp[ r      * 32 + c0];
            const float v1 = acc[g][1] + rp[ r      * 32 + c1];
            const float v2 = acc[g][2] + rp[(r + 8) * 32 + c0];
            const float v3 = acc[g][3] + rp[(r + 8) * 32 + c1];
            const size_t o0 = (((size_t)b * CVAL + c0) << 12) + mg;
            const size_t o1 = (((size_t)b * CVAL + c1) << 12) + mg;
            out[o0]     = fmaxf(2.0f * v0 * para[((size_t)c0 << 12) + mg],     0.0f);
            out[o1]     = fmaxf(2.0f * v1 * para[((size_t)c1 << 12) + mg],     0.0f);
            out[o0 + 8] = fmaxf(2.0f * v2 * para[((size_t)c0 << 12) + mg + 8], 0.0f);
            out[o1 + 8] = fmaxf(2.0f * v3 * para[((size_t)c1 << 12) + mg + 8], 0.0f);
        }
    }
}

// ---------------------------------------------------------------------------
extern "C" void kernel_launch(void* const* d_in, const int* in_sizes, int n_in,
                              void* d_out, int out_size) {
    const float* x    = (const float*)d_in[0];   // [8,32,64,64]
    const float* para = (const float*)d_in[1];   // [1,32,64,64]
    const float* adj  = (const float*)d_in[2];   // [4096,4096]
    float*       out  = (float*)d_out;           // [8,32,64,64]
    (void)in_sizes; (void)n_in; (void)out_size;

    cudaFuncSetAttribute(gcn_hmma_kernel,
                         cudaFuncAttributeMaxDynamicSharedMemorySize, SM_TOTAL);

    prep_kernel<<<(BVAL * NSIZE / 4 + 255) / 256, 256>>>(x);

    dim3 grid(NSIZE / MT, BVAL);                 // 32 x 8 = 256 CTAs
    gcn_hmma_kernel<<<grid, NTHR, SM_TOTAL>>>(para, adj, out);
}